// round 14
// baseline (speedup 1.0000x reference)
#include <cuda_runtime.h>
#include <cuda_fp16.h>
#include <cstdint>

#define N_CAP 100000
#define E_CAP 1600000

// ---------------- scratch (__device__ globals, zero-initialized) ----------------
__device__ float  g_dinv[2][N_CAP];
__device__ int    g_deg[2][N_CAP];        // zero at entry; scan3 re-zeroes
__device__ int    g_incl[2][N_CAP];
__device__ int    g_rowptr[2][N_CAP + 1];
__device__ int    g_bsum[2][128];
__device__ int    g_rank[2][E_CAP];       // per-edge rank within its dst row
__device__ int    g_esrc[2][E_CAP];       // dst-sorted src ids
__device__ __half g_A[2][(size_t)N_CAP * 64];   // h' = dinv * (X @ W), fp16
__device__ float  g_B[2][(size_t)N_CAP * 64];   // Z1 (fp32)

static __device__ __forceinline__ int clampi(int v, int lo, int hi) {
    return v < lo ? lo : (v > hi ? hi : v);
}

// ---------------- hist: per-edge rank claim (4 edges/thread, atomic MLP) ---------

__global__ void hist_kernel(const int* __restrict__ e0, const int* __restrict__ e1,
                            int E, int n) {
    int g = blockIdx.y;
    const int* dst = (g == 0 ? e0 : e1) + E;
    int base_e = blockIdx.x * 1024 + threadIdx.x;
#pragma unroll
    for (int k = 0; k < 4; k++) {
        int e = base_e + k * 256;
        if (e < E) {
            int d = clampi(dst[e], 0, n - 1);
            g_rank[g][e] = atomicAdd(&g_deg[g][d], 1);
        }
    }
}

// ---------------- scan1: per-1024-chunk inclusive scan + dinv ----------------

__global__ void scan1_kernel(int n) {
    __shared__ int sh[1024];
    int g = blockIdx.y;
    int i = blockIdx.x * 1024 + threadIdx.x;
    int v = (i < n) ? g_deg[g][i] : 0;
    if (i < n) g_dinv[g][i] = rsqrtf((float)v + 1.0f);  // self-loop
    sh[threadIdx.x] = v;
    __syncthreads();
#pragma unroll
    for (int off = 1; off < 1024; off <<= 1) {
        int t = (threadIdx.x >= off) ? sh[threadIdx.x - off] : 0;
        __syncthreads();
        sh[threadIdx.x] += t;
        __syncthreads();
    }
    if (i < n) g_incl[g][i] = sh[threadIdx.x];
    if (threadIdx.x == 1023) g_bsum[g][blockIdx.x] = sh[1023];
}

// ---------------- scan3: rowptr finalize + deg reset ----------------

__global__ void scan3_kernel(int n, int E) {
    __shared__ int sh_off;
    int g = blockIdx.y;
    int t = threadIdx.x;
    int chunk = (blockIdx.x * 256) >> 10;
    if (t < 32) {
        int s = 0;
        for (int k = t; k < chunk; k += 32) s += g_bsum[g][k];
#pragma unroll
        for (int o = 16; o; o >>= 1) s += __shfl_down_sync(0xFFFFFFFFu, s, o);
        if (t == 0) sh_off = s;
    }
    __syncthreads();
    int off = sh_off;
    int i = blockIdx.x * 256 + t;
    if (i < n) {
        g_rowptr[g][i] = g_incl[g][i] - g_deg[g][i] + off;  // exclusive
        g_deg[g][i] = 0;                                     // reset invariant
    }
    if (i == 0) g_rowptr[g][n] = E;
}

// ---------------- claim: atomic-free CSR scatter (4 edges/thread MLP) ------------

__global__ void claim_kernel(const int* __restrict__ e0, const int* __restrict__ e1,
                             int E, int n) {
    int g = blockIdx.y;
    const int* base = (g == 0 ? e0 : e1);
    int base_e = blockIdx.x * 1024 + threadIdx.x;
#pragma unroll
    for (int k = 0; k < 4; k++) {
        int e = base_e + k * 256;
        if (e < E) {
            int s = clampi(base[e], 0, n - 1);
            int d = clampi(base[E + e], 0, n - 1);
            int pos = g_rowptr[g][d] + g_rank[g][e];
            g_esrc[g][pos] = s;
        }
    }
}

// ---------------- GEMM (merged, layer 1): h' = dinv * (X @ W1), fp16 -------------

__global__ void gemm1_kernel(const float* __restrict__ X0, const float* __restrict__ X1,
                             const float* __restrict__ W, int n) {
    __shared__ float Ws[64][64];
    __shared__ float Xs[64][65];
    int g = blockIdx.y;
    const float* X = (g == 0 ? X0 : X1);
    __half* Y = g_A[g];
    int tid = threadIdx.x;
    for (int i = tid; i < 64 * 16; i += 256)
        ((float4*)Ws)[i] = ((const float4*)W)[i];
    int row0 = blockIdx.x * 64;
    for (int i = tid; i < 64 * 16; i += 256) {
        int r = i >> 4, c = (i & 15) * 4;
        float4 v = make_float4(0.f, 0.f, 0.f, 0.f);
        if (row0 + r < n) v = *(const float4*)&X[(size_t)(row0 + r) * 64 + c];
        Xs[r][c] = v.x; Xs[r][c + 1] = v.y; Xs[r][c + 2] = v.z; Xs[r][c + 3] = v.w;
    }
    __syncthreads();
    int tr = (tid >> 4) * 4;
    int tc = tid & 15;
    float acc[4][4] = {};
#pragma unroll
    for (int k = 0; k < 64; k++) {
        float4 w4 = ((const float4*)&Ws[k][0])[tc];
        float x0 = Xs[tr + 0][k], x1 = Xs[tr + 1][k];
        float x2 = Xs[tr + 2][k], x3 = Xs[tr + 3][k];
        acc[0][0] += x0 * w4.x; acc[0][1] += x0 * w4.y; acc[0][2] += x0 * w4.z; acc[0][3] += x0 * w4.w;
        acc[1][0] += x1 * w4.x; acc[1][1] += x1 * w4.y; acc[1][2] += x1 * w4.z; acc[1][3] += x1 * w4.w;
        acc[2][0] += x2 * w4.x; acc[2][1] += x2 * w4.y; acc[2][2] += x2 * w4.z; acc[2][3] += x2 * w4.w;
        acc[3][0] += x3 * w4.x; acc[3][1] += x3 * w4.y; acc[3][2] += x3 * w4.z; acc[3][3] += x3 * w4.w;
    }
#pragma unroll
    for (int i = 0; i < 4; i++) {
        int r = row0 + tr + i;
        if (r < n) {
            float dv = g_dinv[g][r];
            __half2 p0 = __floats2half2_rn(acc[i][0] * dv, acc[i][1] * dv);
            __half2 p1 = __floats2half2_rn(acc[i][2] * dv, acc[i][3] * dv);
            uint2 u = make_uint2(*(unsigned*)&p0, *(unsigned*)&p1);
            *(uint2*)&Y[(size_t)r * 64 + tc * 4] = u;
        }
    }
}

// ---------------- GEMM (per-graph, layer 2): h' = dinv * (relu(Z1) @ W2) ---------

__global__ void gemm2_kernel(int g, const float* __restrict__ W, int n) {
    __shared__ float Ws[64][64];
    __shared__ float Xs[64][65];
    const float* X = g_B[g];
    __half* Y = g_A[g];
    int tid = threadIdx.x;
    for (int i = tid; i < 64 * 16; i += 256)
        ((float4*)Ws)[i] = ((const float4*)W)[i];
    int row0 = blockIdx.x * 64;
    for (int i = tid; i < 64 * 16; i += 256) {
        int r = i >> 4, c = (i & 15) * 4;
        float4 v = make_float4(0.f, 0.f, 0.f, 0.f);
        if (row0 + r < n) v = *(const float4*)&X[(size_t)(row0 + r) * 64 + c];
        v.x = fmaxf(v.x, 0.f); v.y = fmaxf(v.y, 0.f);
        v.z = fmaxf(v.z, 0.f); v.w = fmaxf(v.w, 0.f);
        Xs[r][c] = v.x; Xs[r][c + 1] = v.y; Xs[r][c + 2] = v.z; Xs[r][c + 3] = v.w;
    }
    __syncthreads();
    int tr = (tid >> 4) * 4;
    int tc = tid & 15;
    float acc[4][4] = {};
#pragma unroll
    for (int k = 0; k < 64; k++) {
        float4 w4 = ((const float4*)&Ws[k][0])[tc];
        float x0 = Xs[tr + 0][k], x1 = Xs[tr + 1][k];
        float x2 = Xs[tr + 2][k], x3 = Xs[tr + 3][k];
        acc[0][0] += x0 * w4.x; acc[0][1] += x0 * w4.y; acc[0][2] += x0 * w4.z; acc[0][3] += x0 * w4.w;
        acc[1][0] += x1 * w4.x; acc[1][1] += x1 * w4.y; acc[1][2] += x1 * w4.z; acc[1][3] += x1 * w4.w;
        acc[2][0] += x2 * w4.x; acc[2][1] += x2 * w4.y; acc[2][2] += x2 * w4.z; acc[2][3] += x2 * w4.w;
        acc[3][0] += x3 * w4.x; acc[3][1] += x3 * w4.y; acc[3][2] += x3 * w4.z; acc[3][3] += x3 * w4.w;
    }
#pragma unroll
    for (int i = 0; i < 4; i++) {
        int r = row0 + tr + i;
        if (r < n) {
            float dv = g_dinv[g][r];
            __half2 p0 = __floats2half2_rn(acc[i][0] * dv, acc[i][1] * dv);
            __half2 p1 = __floats2half2_rn(acc[i][2] * dv, acc[i][3] * dv);
            uint2 u = make_uint2(*(unsigned*)&p0, *(unsigned*)&p1);
            *(uint2*)&Y[(size_t)r * 64 + tc * 4] = u;
        }
    }
}

// ---------------- aggregation (per-graph): Z = dinv[d]*(Σ h'[src] + h'[d]) + b ---
// R9 shape: warp per node; lanes split 16/16, each load covers TWO edge rows.

__global__ void agg_kernel(int g, const float* __restrict__ b, int n,
                           const float* __restrict__ Wy, const float* __restrict__ by,
                           const float* __restrict__ Wp, const float* __restrict__ bp,
                           const float* __restrict__ Wb, const float* __restrict__ bb,
                           float* __restrict__ out) {
    int node = (blockIdx.x * blockDim.x + threadIdx.x) >> 5;
    int lane = threadIdx.x & 31;
    if (node >= n) return;
    const uint2* __restrict__ h4 = (const uint2*)g_A[g];
    const int*   __restrict__ ep = g_esrc[g];

    int half = lane >> 4;
    int c4   = lane & 15;
    float a0 = 0.f, a1 = 0.f, a2 = 0.f, a3 = 0.f;

    int beg = g_rowptr[g][node];
    int end = g_rowptr[g][node + 1];

    for (int jj = beg; jj < end; jj += 8) {
#pragma unroll
        for (int s = 0; s < 4; s++) {
            int my = jj + s * 2 + half;
            if (my < end) {
                int src = ep[my];
                uint2 u = h4[(size_t)src * 16 + c4];
                float2 f0 = __half22float2(*(__half2*)&u.x);
                float2 f1 = __half22float2(*(__half2*)&u.y);
                a0 += f0.x; a1 += f0.y; a2 += f1.x; a3 += f1.y;
            }
        }
    }
    a0 += __shfl_xor_sync(0xFFFFFFFFu, a0, 16);
    a1 += __shfl_xor_sync(0xFFFFFFFFu, a1, 16);
    a2 += __shfl_xor_sync(0xFFFFFFFFu, a2, 16);
    a3 += __shfl_xor_sync(0xFFFFFFFFu, a3, 16);

    uint2 us = h4[(size_t)node * 16 + c4];
    float2 s0 = __half22float2(*(__half2*)&us.x);
    float2 s1 = __half22float2(*(__half2*)&us.y);
    float dd = g_dinv[g][node];
    const float4 bv = *(const float4*)&b[c4 * 4];
    float z0 = fmaf(dd, a0 + s0.x, bv.x);
    float z1 = fmaf(dd, a1 + s0.y, bv.y);
    float z2 = fmaf(dd, a2 + s1.x, bv.z);
    float z3 = fmaf(dd, a3 + s1.y, bv.w);

    if (!Wy) {  // layer 1
        if (half == 0)
            *(float4*)&g_B[g][(size_t)node * 64 + c4 * 4] = make_float4(z0, z1, z2, z3);
        return;
    }
    if (g == 0) {
        float4 wy = *(const float4*)&Wy[c4 * 4];
        float4 wp = *(const float4*)&Wp[c4 * 4];
        float4 wb = *(const float4*)&Wb[c4 * 4];
        float sy = z0 * wy.x + z1 * wy.y + z2 * wy.z + z3 * wy.w;
        float sp = z0 * wp.x + z1 * wp.y + z2 * wp.z + z3 * wp.w;
        float sb = z0 * wb.x + z1 * wb.y + z2 * wb.z + z3 * wb.w;
#pragma unroll
        for (int o = 8; o; o >>= 1) {
            sy += __shfl_down_sync(0xFFFFFFFFu, sy, o, 16);
            sp += __shfl_down_sync(0xFFFFFFFFu, sp, o, 16);
            sb += __shfl_down_sync(0xFFFFFFFFu, sb, o, 16);
        }
        if (lane == 0) {
            out[node]                 = fmaxf(sy + by[0], 0.f);  // yi
            out[(size_t)n + node]     = fmaxf(sp + bp[0], 0.f);  // fprob
            out[(size_t)3 * n + node] = fmaxf(sb + bb[0], 0.f);  // treat_prob
        }
    } else {
        float4 wp = *(const float4*)&Wp[c4 * 4];
        float sf = z0 * wp.x + z1 * wp.y + z2 * wp.z + z3 * wp.w;
#pragma unroll
        for (int o = 8; o; o >>= 1)
            sf += __shfl_down_sync(0xFFFFFFFFu, sf, o, 16);
        if (lane == 0)
            out[(size_t)2 * n + node] = fmaxf(sf + bp[0], 0.f);  // fprob_f
    }
}

// ---------------- launch ----------------

extern "C" void kernel_launch(void* const* d_in, const int* in_sizes, int n_in,
                              void* d_out, int out_size) {
    const float* x   = (const float*)d_in[0];
    const int*   ei  = (const int*)d_in[1];    // int32 on the wire
    const float* fx  = (const float*)d_in[2];
    const int*   fei = (const int*)d_in[3];
    const float* W1 = (const float*)d_in[4];
    const float* b1 = (const float*)d_in[5];
    const float* W2 = (const float*)d_in[6];
    const float* b2 = (const float*)d_in[7];
    const float* Wy = (const float*)d_in[8];
    const float* by = (const float*)d_in[9];
    const float* Wp = (const float*)d_in[10];
    const float* bp = (const float*)d_in[11];
    const float* Wb = (const float*)d_in[12];
    const float* bb = (const float*)d_in[13];

    int n = in_sizes[0] / 64;
    int E = in_sizes[1] / 2;
    float* out = (float*)d_out;

    // side stream + events (created on uncaptured correctness call, reused in capture)
    static cudaStream_t s2 = nullptr;
    static cudaEvent_t ev_fork = nullptr, ev_gemm1 = nullptr, ev_csr = nullptr, ev_end = nullptr;
    if (!s2) {
        cudaStreamCreateWithFlags(&s2, cudaStreamNonBlocking);
        cudaEventCreateWithFlags(&ev_fork, cudaEventDisableTiming);
        cudaEventCreateWithFlags(&ev_gemm1, cudaEventDisableTiming);
        cudaEventCreateWithFlags(&ev_csr, cudaEventDisableTiming);
        cudaEventCreateWithFlags(&ev_end, cudaEventDisableTiming);
    }

    dim3 ge4((E + 1023) / 1024, 2);
    dim3 gs((n + 1023) / 1024, 2);
    dim3 g3((n + 255) / 256, 2);
    dim3 gg2((n + 63) / 64, 2);
    int nb_g = (n + 63) / 64;
    int nb_w = (n * 32 + 255) / 256;

    // ---- CSR head (merged, stream 0) ----
    hist_kernel<<<ge4, 256>>>(ei, fei, E, n);
    scan1_kernel<<<gs, 1024>>>(n);

    // fork: gemm1 (both graphs) on s2, overlapping scan3+claim
    cudaEventRecord(ev_fork, 0);
    cudaStreamWaitEvent(s2, ev_fork, 0);
    gemm1_kernel<<<gg2, 256, 0, s2>>>(x, fx, W1, n);
    cudaEventRecord(ev_gemm1, s2);

    scan3_kernel<<<g3, 256>>>(n, E);
    claim_kernel<<<ge4, 256>>>(ei, fei, E, n);
    cudaEventRecord(ev_csr, 0);

    // ---- per-graph tails on two streams ----
    // stream 0: graph 0 (needs gemm1 from s2)
    cudaStreamWaitEvent(0, ev_gemm1, 0);
    agg_kernel<<<nb_w, 256>>>(0, b1, n, nullptr, nullptr, nullptr, nullptr, nullptr, nullptr, nullptr);
    gemm2_kernel<<<nb_g, 256>>>(0, W2, n);
    agg_kernel<<<nb_w, 256>>>(0, b2, n, Wy, by, Wp, bp, Wb, bb, out);

    // stream s2: graph 1 (needs CSR from stream 0; gemm1 already in-stream)
    cudaStreamWaitEvent(s2, ev_csr, 0);
    agg_kernel<<<nb_w, 256, 0, s2>>>(1, b1, n, nullptr, nullptr, nullptr, nullptr, nullptr, nullptr, nullptr);
    gemm2_kernel<<<nb_g, 256, 0, s2>>>(1, W2, n);
    agg_kernel<<<nb_w, 256, 0, s2>>>(1, b2, n, Wy, by, Wp, bp, Wb, bb, out);
    cudaEventRecord(ev_end, s2);

    // join: harness syncs stream 0
    cudaStreamWaitEvent(0, ev_end, 0);
}

// round 15
// speedup vs baseline: 1.3559x; 1.3559x over previous
#include <cuda_runtime.h>
#include <cuda_fp16.h>
#include <cstdint>

#define N_CAP 100000
#define E_CAP 1600000

// ---------------- scratch (__device__ globals, zero-initialized) ----------------
__device__ float  g_dinv[2][N_CAP];
__device__ int    g_deg[2][N_CAP];        // zero at entry; scan3 re-zeroes
__device__ int    g_incl[2][N_CAP];
__device__ int    g_rowptr[2][N_CAP + 1];
__device__ int    g_bsum[2][128];
__device__ int    g_rank[2][E_CAP];       // per-edge rank within its dst row
__device__ int    g_esrc[2][E_CAP];       // dst-sorted src ids
__device__ __half g_A[2][(size_t)N_CAP * 64];   // h' = dinv * (X @ W), fp16
__device__ float  g_B[2][(size_t)N_CAP * 64];   // Z1 (fp32)

static __device__ __forceinline__ int clampi(int v, int lo, int hi) {
    return v < lo ? lo : (v > hi ? hi : v);
}

// ---------------- hist: per-edge rank claim (4 edges/thread, atomic MLP) ---------

__global__ void hist_kernel(const int* __restrict__ e0, const int* __restrict__ e1,
                            int E, int n) {
    int g = blockIdx.y;
    const int* dst = (g == 0 ? e0 : e1) + E;
    int base_e = blockIdx.x * 1024 + threadIdx.x;
#pragma unroll
    for (int k = 0; k < 4; k++) {
        int e = base_e + k * 256;
        if (e < E) {
            int d = clampi(dst[e], 0, n - 1);
            g_rank[g][e] = atomicAdd(&g_deg[g][d], 1);
        }
    }
}

// ---------------- scan1: per-1024-chunk inclusive scan + dinv (warp-shuffle) -----

__global__ void scan1_kernel(int n) {
    __shared__ int warp_sums[32];
    int g = blockIdx.y;
    int i = blockIdx.x * 1024 + threadIdx.x;
    int lane = threadIdx.x & 31;
    int wid  = threadIdx.x >> 5;
    int v = (i < n) ? g_deg[g][i] : 0;
    if (i < n) g_dinv[g][i] = rsqrtf((float)v + 1.0f);  // self-loop

    int s = v;
#pragma unroll
    for (int o = 1; o < 32; o <<= 1) {
        int t = __shfl_up_sync(0xFFFFFFFFu, s, o);
        if (lane >= o) s += t;
    }
    if (lane == 31) warp_sums[wid] = s;
    __syncthreads();
    if (wid == 0) {
        int ws = warp_sums[lane];
#pragma unroll
        for (int o = 1; o < 32; o <<= 1) {
            int t = __shfl_up_sync(0xFFFFFFFFu, ws, o);
            if (lane >= o) ws += t;
        }
        warp_sums[lane] = ws;
    }
    __syncthreads();
    if (wid > 0) s += warp_sums[wid - 1];

    if (i < n) g_incl[g][i] = s;
    if (threadIdx.x == 1023) g_bsum[g][blockIdx.x] = s;
}

// ---------------- scan3: rowptr finalize + deg reset ----------------

__global__ void scan3_kernel(int n, int E) {
    __shared__ int sh_off;
    int g = blockIdx.y;
    int t = threadIdx.x;
    int chunk = (blockIdx.x * 256) >> 10;
    if (t < 32) {
        int s = 0;
        for (int k = t; k < chunk; k += 32) s += g_bsum[g][k];
#pragma unroll
        for (int o = 16; o; o >>= 1) s += __shfl_down_sync(0xFFFFFFFFu, s, o);
        if (t == 0) sh_off = s;
    }
    __syncthreads();
    int off = sh_off;
    int i = blockIdx.x * 256 + t;
    if (i < n) {
        g_rowptr[g][i] = g_incl[g][i] - g_deg[g][i] + off;  // exclusive
        g_deg[g][i] = 0;                                     // reset invariant
    }
    if (i == 0) g_rowptr[g][n] = E;
}

// ---------------- claim: atomic-free CSR scatter (4 edges/thread MLP) ------------

__global__ void claim_kernel(const int* __restrict__ e0, const int* __restrict__ e1,
                             int E, int n) {
    int g = blockIdx.y;
    const int* base = (g == 0 ? e0 : e1);
    int base_e = blockIdx.x * 1024 + threadIdx.x;
#pragma unroll
    for (int k = 0; k < 4; k++) {
        int e = base_e + k * 256;
        if (e < E) {
            int s = clampi(base[e], 0, n - 1);
            int d = clampi(base[E + e], 0, n - 1);
            int pos = g_rowptr[g][d] + g_rank[g][e];
            g_esrc[g][pos] = s;
        }
    }
}

// ---------------- GEMM: h' = dinv * ((relu?)X @ W), fp16 out ----------------

__global__ void gemm64_kernel(const float* __restrict__ X0, const float* __restrict__ X1,
                              int use_B, const float* __restrict__ W, int n, int relu_in) {
    __shared__ float Ws[64][64];
    __shared__ float Xs[64][65];
    int g = blockIdx.y;
    const float* X = use_B ? (const float*)g_B[g] : (g == 0 ? X0 : X1);
    __half* Y = g_A[g];
    int tid = threadIdx.x;
    for (int i = tid; i < 64 * 16; i += 256)
        ((float4*)Ws)[i] = ((const float4*)W)[i];
    int row0 = blockIdx.x * 64;
    for (int i = tid; i < 64 * 16; i += 256) {
        int r = i >> 4, c = (i & 15) * 4;
        float4 v = make_float4(0.f, 0.f, 0.f, 0.f);
        if (row0 + r < n) v = *(const float4*)&X[(size_t)(row0 + r) * 64 + c];
        if (relu_in) {
            v.x = fmaxf(v.x, 0.f); v.y = fmaxf(v.y, 0.f);
            v.z = fmaxf(v.z, 0.f); v.w = fmaxf(v.w, 0.f);
        }
        Xs[r][c] = v.x; Xs[r][c + 1] = v.y; Xs[r][c + 2] = v.z; Xs[r][c + 3] = v.w;
    }
    __syncthreads();
    int tr = (tid >> 4) * 4;
    int tc = tid & 15;
    float acc[4][4] = {};
#pragma unroll
    for (int k = 0; k < 64; k++) {
        float4 w4 = ((const float4*)&Ws[k][0])[tc];
        float x0 = Xs[tr + 0][k], x1 = Xs[tr + 1][k];
        float x2 = Xs[tr + 2][k], x3 = Xs[tr + 3][k];
        acc[0][0] += x0 * w4.x; acc[0][1] += x0 * w4.y; acc[0][2] += x0 * w4.z; acc[0][3] += x0 * w4.w;
        acc[1][0] += x1 * w4.x; acc[1][1] += x1 * w4.y; acc[1][2] += x1 * w4.z; acc[1][3] += x1 * w4.w;
        acc[2][0] += x2 * w4.x; acc[2][1] += x2 * w4.y; acc[2][2] += x2 * w4.z; acc[2][3] += x2 * w4.w;
        acc[3][0] += x3 * w4.x; acc[3][1] += x3 * w4.y; acc[3][2] += x3 * w4.z; acc[3][3] += x3 * w4.w;
    }
#pragma unroll
    for (int i = 0; i < 4; i++) {
        int r = row0 + tr + i;
        if (r < n) {
            float dv = g_dinv[g][r];
            __half2 p0 = __floats2half2_rn(acc[i][0] * dv, acc[i][1] * dv);
            __half2 p1 = __floats2half2_rn(acc[i][2] * dv, acc[i][3] * dv);
            uint2 u = make_uint2(*(unsigned*)&p0, *(unsigned*)&p1);
            *(uint2*)&Y[(size_t)r * 64 + tc * 4] = u;
        }
    }
}

// ---------------- aggregation: Z = dinv[d]*(Σ h'[src] + h'[d]) + b ----------------
// R9 shape (confirmed optimum): warp per node; 16/16 lane split, 2 edge rows/load.

__global__ void agg_kernel(const float* __restrict__ b, int n,
                           const float* __restrict__ Wy, const float* __restrict__ by,
                           const float* __restrict__ Wp, const float* __restrict__ bp,
                           const float* __restrict__ Wb, const float* __restrict__ bb,
                           float* __restrict__ out) {
    int g = blockIdx.y;
    int node = (blockIdx.x * blockDim.x + threadIdx.x) >> 5;
    int lane = threadIdx.x & 31;
    if (node >= n) return;
    const uint2* __restrict__ h4 = (const uint2*)g_A[g];
    const int*   __restrict__ ep = g_esrc[g];

    int half = lane >> 4;
    int c4   = lane & 15;
    float a0 = 0.f, a1 = 0.f, a2 = 0.f, a3 = 0.f;

    int beg = g_rowptr[g][node];
    int end = g_rowptr[g][node + 1];

    for (int jj = beg; jj < end; jj += 8) {
#pragma unroll
        for (int s = 0; s < 4; s++) {
            int my = jj + s * 2 + half;
            if (my < end) {
                int src = ep[my];
                uint2 u = h4[(size_t)src * 16 + c4];
                float2 f0 = __half22float2(*(__half2*)&u.x);
                float2 f1 = __half22float2(*(__half2*)&u.y);
                a0 += f0.x; a1 += f0.y; a2 += f1.x; a3 += f1.y;
            }
        }
    }
    a0 += __shfl_xor_sync(0xFFFFFFFFu, a0, 16);
    a1 += __shfl_xor_sync(0xFFFFFFFFu, a1, 16);
    a2 += __shfl_xor_sync(0xFFFFFFFFu, a2, 16);
    a3 += __shfl_xor_sync(0xFFFFFFFFu, a3, 16);

    uint2 us = h4[(size_t)node * 16 + c4];
    float2 s0 = __half22float2(*(__half2*)&us.x);
    float2 s1 = __half22float2(*(__half2*)&us.y);
    float dd = g_dinv[g][node];
    const float4 bv = *(const float4*)&b[c4 * 4];
    float z0 = fmaf(dd, a0 + s0.x, bv.x);
    float z1 = fmaf(dd, a1 + s0.y, bv.y);
    float z2 = fmaf(dd, a2 + s1.x, bv.z);
    float z3 = fmaf(dd, a3 + s1.y, bv.w);

    if (!Wy) {  // layer 1
        if (half == 0)
            *(float4*)&g_B[g][(size_t)node * 64 + c4 * 4] = make_float4(z0, z1, z2, z3);
        return;
    }
    if (g == 0) {
        float4 wy = *(const float4*)&Wy[c4 * 4];
        float4 wp = *(const float4*)&Wp[c4 * 4];
        float4 wb = *(const float4*)&Wb[c4 * 4];
        float sy = z0 * wy.x + z1 * wy.y + z2 * wy.z + z3 * wy.w;
        float sp = z0 * wp.x + z1 * wp.y + z2 * wp.z + z3 * wp.w;
        float sb = z0 * wb.x + z1 * wb.y + z2 * wb.z + z3 * wb.w;
#pragma unroll
        for (int o = 8; o; o >>= 1) {
            sy += __shfl_down_sync(0xFFFFFFFFu, sy, o, 16);
            sp += __shfl_down_sync(0xFFFFFFFFu, sp, o, 16);
            sb += __shfl_down_sync(0xFFFFFFFFu, sb, o, 16);
        }
        if (lane == 0) {
            out[node]                 = fmaxf(sy + by[0], 0.f);  // yi
            out[(size_t)n + node]     = fmaxf(sp + bp[0], 0.f);  // fprob
            out[(size_t)3 * n + node] = fmaxf(sb + bb[0], 0.f);  // treat_prob
        }
    } else {
        float4 wp = *(const float4*)&Wp[c4 * 4];
        float sf = z0 * wp.x + z1 * wp.y + z2 * wp.z + z3 * wp.w;
#pragma unroll
        for (int o = 8; o; o >>= 1)
            sf += __shfl_down_sync(0xFFFFFFFFu, sf, o, 16);
        if (lane == 0)
            out[(size_t)2 * n + node] = fmaxf(sf + bp[0], 0.f);  // fprob_f
    }
}

// ---------------- launch (R13 structure: single fork for gemm1 only) -------------

extern "C" void kernel_launch(void* const* d_in, const int* in_sizes, int n_in,
                              void* d_out, int out_size) {
    const float* x   = (const float*)d_in[0];
    const int*   ei  = (const int*)d_in[1];    // int32 on the wire
    const float* fx  = (const float*)d_in[2];
    const int*   fei = (const int*)d_in[3];
    const float* W1 = (const float*)d_in[4];
    const float* b1 = (const float*)d_in[5];
    const float* W2 = (const float*)d_in[6];
    const float* b2 = (const float*)d_in[7];
    const float* Wy = (const float*)d_in[8];
    const float* by = (const float*)d_in[9];
    const float* Wp = (const float*)d_in[10];
    const float* bp = (const float*)d_in[11];
    const float* Wb = (const float*)d_in[12];
    const float* bb = (const float*)d_in[13];

    int n = in_sizes[0] / 64;
    int E = in_sizes[1] / 2;
    float* out = (float*)d_out;

    static cudaStream_t s2 = nullptr;
    static cudaEvent_t ev_fork = nullptr, ev_join = nullptr;
    if (!s2) {
        cudaStreamCreateWithFlags(&s2, cudaStreamNonBlocking);
        cudaEventCreateWithFlags(&ev_fork, cudaEventDisableTiming);
        cudaEventCreateWithFlags(&ev_join, cudaEventDisableTiming);
    }

    dim3 ge4((E + 1023) / 1024, 2);
    dim3 gs((n + 1023) / 1024, 2);
    dim3 g3((n + 255) / 256, 2);
    dim3 gg((n + 63) / 64, 2);
    dim3 gw((n * 32 + 255) / 256, 2);

    // CSR build head
    hist_kernel<<<ge4, 256>>>(ei, fei, E, n);      // rank claim
    scan1_kernel<<<gs, 1024>>>(n);                 // deg scan + dinv (warp-shuffle)

    // fork: gemm1 (needs only dinv) overlaps scan3 + claim
    cudaEventRecord(ev_fork, 0);
    cudaStreamWaitEvent(s2, ev_fork, 0);
    gemm64_kernel<<<gg, 256, 0, s2>>>(x, fx, 0, W1, n, 0);
    cudaEventRecord(ev_join, s2);

    scan3_kernel<<<g3, 256>>>(n, E);               // rowptr + deg reset
    claim_kernel<<<ge4, 256>>>(ei, fei, E, n);     // atomic-free CSR scatter

    cudaStreamWaitEvent(0, ev_join, 0);
    agg_kernel<<<gw, 256>>>(b1, n, nullptr, nullptr, nullptr, nullptr, nullptr, nullptr, nullptr);

    // layer 2 (+ fused heads)
    gemm64_kernel<<<gg, 256>>>(nullptr, nullptr, 1, W2, n, 1);
    agg_kernel<<<gw, 256>>>(b2, n, Wy, by, Wp, bp, Wb, bb, out);
}

// round 16
// speedup vs baseline: 1.3562x; 1.0002x over previous
#include <cuda_runtime.h>
#include <cuda_fp16.h>
#include <cstdint>

#define N_CAP 100000
#define E_CAP 1600000

// ---------------- scratch (__device__ globals, zero-initialized) ----------------
__device__ float  g_dinv[2][N_CAP];
__device__ int    g_deg[2][N_CAP];        // zero at entry; scan3 re-zeroes
__device__ int    g_incl[2][N_CAP];
__device__ int    g_rowptr[2][N_CAP + 1];
__device__ int    g_bsum[2][128];
__device__ int    g_rank[2][E_CAP];       // per-edge rank within its dst row
__device__ int    g_esrc[2][E_CAP];       // dst-sorted src ids
__device__ __half g_A[2][(size_t)N_CAP * 64];   // h' = dinv * (X @ W), fp16
__device__ float  g_B[2][(size_t)N_CAP * 64];   // Z1 (fp32)

static __device__ __forceinline__ int clampi(int v, int lo, int hi) {
    return v < lo ? lo : (v > hi ? hi : v);
}

// ---------------- hist: per-edge rank claim (4 edges/thread, atomic MLP) ---------

__global__ void hist_kernel(const int* __restrict__ e0, const int* __restrict__ e1,
                            int E, int n) {
    int g = blockIdx.y;
    const int* dst = (g == 0 ? e0 : e1) + E;
    int base_e = blockIdx.x * 1024 + threadIdx.x;
#pragma unroll
    for (int k = 0; k < 4; k++) {
        int e = base_e + k * 256;
        if (e < E) {
            int d = clampi(dst[e], 0, n - 1);
            g_rank[g][e] = atomicAdd(&g_deg[g][d], 1);
        }
    }
}

// ---------------- scan1: per-1024-chunk inclusive scan + dinv (warp-shuffle) -----

__global__ void scan1_kernel(int n) {
    __shared__ int warp_sums[32];
    int g = blockIdx.y;
    int i = blockIdx.x * 1024 + threadIdx.x;
    int lane = threadIdx.x & 31;
    int wid  = threadIdx.x >> 5;
    int v = (i < n) ? g_deg[g][i] : 0;
    if (i < n) g_dinv[g][i] = rsqrtf((float)v + 1.0f);  // self-loop

    int s = v;
#pragma unroll
    for (int o = 1; o < 32; o <<= 1) {
        int t = __shfl_up_sync(0xFFFFFFFFu, s, o);
        if (lane >= o) s += t;
    }
    if (lane == 31) warp_sums[wid] = s;
    __syncthreads();
    if (wid == 0) {
        int ws = warp_sums[lane];
#pragma unroll
        for (int o = 1; o < 32; o <<= 1) {
            int t = __shfl_up_sync(0xFFFFFFFFu, ws, o);
            if (lane >= o) ws += t;
        }
        warp_sums[lane] = ws;
    }
    __syncthreads();
    if (wid > 0) s += warp_sums[wid - 1];

    if (i < n) g_incl[g][i] = s;
    if (threadIdx.x == 1023) g_bsum[g][blockIdx.x] = s;
}

// ---------------- scan3: rowptr finalize + deg reset ----------------

__global__ void scan3_kernel(int n, int E) {
    __shared__ int sh_off;
    int g = blockIdx.y;
    int t = threadIdx.x;
    int chunk = (blockIdx.x * 256) >> 10;
    if (t < 32) {
        int s = 0;
        for (int k = t; k < chunk; k += 32) s += g_bsum[g][k];
#pragma unroll
        for (int o = 16; o; o >>= 1) s += __shfl_down_sync(0xFFFFFFFFu, s, o);
        if (t == 0) sh_off = s;
    }
    __syncthreads();
    int off = sh_off;
    int i = blockIdx.x * 256 + t;
    if (i < n) {
        g_rowptr[g][i] = g_incl[g][i] - g_deg[g][i] + off;  // exclusive
        g_deg[g][i] = 0;                                     // reset invariant
    }
    if (i == 0) g_rowptr[g][n] = E;
}

// ---------------- claim: atomic-free CSR scatter (4 edges/thread MLP) ------------

__global__ void claim_kernel(const int* __restrict__ e0, const int* __restrict__ e1,
                             int E, int n) {
    int g = blockIdx.y;
    const int* base = (g == 0 ? e0 : e1);
    int base_e = blockIdx.x * 1024 + threadIdx.x;
#pragma unroll
    for (int k = 0; k < 4; k++) {
        int e = base_e + k * 256;
        if (e < E) {
            int s = clampi(base[e], 0, n - 1);
            int d = clampi(base[E + e], 0, n - 1);
            int pos = g_rowptr[g][d] + g_rank[g][e];
            g_esrc[g][pos] = s;
        }
    }
}

// ---------------- GEMM: h' = dinv * ((relu?)X @ W), fp16 out ----------------

__global__ void gemm64_kernel(const float* __restrict__ X0, const float* __restrict__ X1,
                              int use_B, const float* __restrict__ W, int n, int relu_in) {
    __shared__ float Ws[64][64];
    __shared__ float Xs[64][65];
    int g = blockIdx.y;
    const float* X = use_B ? (const float*)g_B[g] : (g == 0 ? X0 : X1);
    __half* Y = g_A[g];
    int tid = threadIdx.x;
    for (int i = tid; i < 64 * 16; i += 256)
        ((float4*)Ws)[i] = ((const float4*)W)[i];
    int row0 = blockIdx.x * 64;
    for (int i = tid; i < 64 * 16; i += 256) {
        int r = i >> 4, c = (i & 15) * 4;
        float4 v = make_float4(0.f, 0.f, 0.f, 0.f);
        if (row0 + r < n) v = *(const float4*)&X[(size_t)(row0 + r) * 64 + c];
        if (relu_in) {
            v.x = fmaxf(v.x, 0.f); v.y = fmaxf(v.y, 0.f);
            v.z = fmaxf(v.z, 0.f); v.w = fmaxf(v.w, 0.f);
        }
        Xs[r][c] = v.x; Xs[r][c + 1] = v.y; Xs[r][c + 2] = v.z; Xs[r][c + 3] = v.w;
    }
    __syncthreads();
    int tr = (tid >> 4) * 4;
    int tc = tid & 15;
    float acc[4][4] = {};
#pragma unroll
    for (int k = 0; k < 64; k++) {
        float4 w4 = ((const float4*)&Ws[k][0])[tc];
        float x0 = Xs[tr + 0][k], x1 = Xs[tr + 1][k];
        float x2 = Xs[tr + 2][k], x3 = Xs[tr + 3][k];
        acc[0][0] += x0 * w4.x; acc[0][1] += x0 * w4.y; acc[0][2] += x0 * w4.z; acc[0][3] += x0 * w4.w;
        acc[1][0] += x1 * w4.x; acc[1][1] += x1 * w4.y; acc[1][2] += x1 * w4.z; acc[1][3] += x1 * w4.w;
        acc[2][0] += x2 * w4.x; acc[2][1] += x2 * w4.y; acc[2][2] += x2 * w4.z; acc[2][3] += x2 * w4.w;
        acc[3][0] += x3 * w4.x; acc[3][1] += x3 * w4.y; acc[3][2] += x3 * w4.z; acc[3][3] += x3 * w4.w;
    }
#pragma unroll
    for (int i = 0; i < 4; i++) {
        int r = row0 + tr + i;
        if (r < n) {
            float dv = g_dinv[g][r];
            __half2 p0 = __floats2half2_rn(acc[i][0] * dv, acc[i][1] * dv);
            __half2 p1 = __floats2half2_rn(acc[i][2] * dv, acc[i][3] * dv);
            uint2 u = make_uint2(*(unsigned*)&p0, *(unsigned*)&p1);
            *(uint2*)&Y[(size_t)r * 64 + tc * 4] = u;
        }
    }
}

// ---------------- aggregation: Z = dinv[d]*(Σ h'[src] + h'[d]) + b ----------------
// R9 shape (confirmed optimum): warp per node; 16/16 lane split, 2 edge rows/load.

__global__ void agg_kernel(const float* __restrict__ b, int n,
                           const float* __restrict__ Wy, const float* __restrict__ by,
                           const float* __restrict__ Wp, const float* __restrict__ bp,
                           const float* __restrict__ Wb, const float* __restrict__ bb,
                           float* __restrict__ out) {
    int g = blockIdx.y;
    int node = (blockIdx.x * blockDim.x + threadIdx.x) >> 5;
    int lane = threadIdx.x & 31;
    if (node >= n) return;
    const uint2* __restrict__ h4 = (const uint2*)g_A[g];
    const int*   __restrict__ ep = g_esrc[g];

    int half = lane >> 4;
    int c4   = lane & 15;
    float a0 = 0.f, a1 = 0.f, a2 = 0.f, a3 = 0.f;

    int beg = g_rowptr[g][node];
    int end = g_rowptr[g][node + 1];

    for (int jj = beg; jj < end; jj += 8) {
#pragma unroll
        for (int s = 0; s < 4; s++) {
            int my = jj + s * 2 + half;
            if (my < end) {
                int src = ep[my];
                uint2 u = h4[(size_t)src * 16 + c4];
                float2 f0 = __half22float2(*(__half2*)&u.x);
                float2 f1 = __half22float2(*(__half2*)&u.y);
                a0 += f0.x; a1 += f0.y; a2 += f1.x; a3 += f1.y;
            }
        }
    }
    a0 += __shfl_xor_sync(0xFFFFFFFFu, a0, 16);
    a1 += __shfl_xor_sync(0xFFFFFFFFu, a1, 16);
    a2 += __shfl_xor_sync(0xFFFFFFFFu, a2, 16);
    a3 += __shfl_xor_sync(0xFFFFFFFFu, a3, 16);

    uint2 us = h4[(size_t)node * 16 + c4];
    float2 s0 = __half22float2(*(__half2*)&us.x);
    float2 s1 = __half22float2(*(__half2*)&us.y);
    float dd = g_dinv[g][node];
    const float4 bv = *(const float4*)&b[c4 * 4];
    float z0 = fmaf(dd, a0 + s0.x, bv.x);
    float z1 = fmaf(dd, a1 + s0.y, bv.y);
    float z2 = fmaf(dd, a2 + s1.x, bv.z);
    float z3 = fmaf(dd, a3 + s1.y, bv.w);

    if (!Wy) {  // layer 1
        if (half == 0)
            *(float4*)&g_B[g][(size_t)node * 64 + c4 * 4] = make_float4(z0, z1, z2, z3);
        return;
    }
    if (g == 0) {
        float4 wy = *(const float4*)&Wy[c4 * 4];
        float4 wp = *(const float4*)&Wp[c4 * 4];
        float4 wb = *(const float4*)&Wb[c4 * 4];
        float sy = z0 * wy.x + z1 * wy.y + z2 * wy.z + z3 * wy.w;
        float sp = z0 * wp.x + z1 * wp.y + z2 * wp.z + z3 * wp.w;
        float sb = z0 * wb.x + z1 * wb.y + z2 * wb.z + z3 * wb.w;
#pragma unroll
        for (int o = 8; o; o >>= 1) {
            sy += __shfl_down_sync(0xFFFFFFFFu, sy, o, 16);
            sp += __shfl_down_sync(0xFFFFFFFFu, sp, o, 16);
            sb += __shfl_down_sync(0xFFFFFFFFu, sb, o, 16);
        }
        if (lane == 0) {
            out[node]                 = fmaxf(sy + by[0], 0.f);  // yi
            out[(size_t)n + node]     = fmaxf(sp + bp[0], 0.f);  // fprob
            out[(size_t)3 * n + node] = fmaxf(sb + bb[0], 0.f);  // treat_prob
        }
    } else {
        float4 wp = *(const float4*)&Wp[c4 * 4];
        float sf = z0 * wp.x + z1 * wp.y + z2 * wp.z + z3 * wp.w;
#pragma unroll
        for (int o = 8; o; o >>= 1)
            sf += __shfl_down_sync(0xFFFFFFFFu, sf, o, 16);
        if (lane == 0)
            out[(size_t)2 * n + node] = fmaxf(sf + bp[0], 0.f);  // fprob_f
    }
}

// ---------------- launch (R13 structure: single fork for gemm1 only) -------------

extern "C" void kernel_launch(void* const* d_in, const int* in_sizes, int n_in,
                              void* d_out, int out_size) {
    const float* x   = (const float*)d_in[0];
    const int*   ei  = (const int*)d_in[1];    // int32 on the wire
    const float* fx  = (const float*)d_in[2];
    const int*   fei = (const int*)d_in[3];
    const float* W1 = (const float*)d_in[4];
    const float* b1 = (const float*)d_in[5];
    const float* W2 = (const float*)d_in[6];
    const float* b2 = (const float*)d_in[7];
    const float* Wy = (const float*)d_in[8];
    const float* by = (const float*)d_in[9];
    const float* Wp = (const float*)d_in[10];
    const float* bp = (const float*)d_in[11];
    const float* Wb = (const float*)d_in[12];
    const float* bb = (const float*)d_in[13];

    int n = in_sizes[0] / 64;
    int E = in_sizes[1] / 2;
    float* out = (float*)d_out;

    static cudaStream_t s2 = nullptr;
    static cudaEvent_t ev_fork = nullptr, ev_join = nullptr;
    if (!s2) {
        cudaStreamCreateWithFlags(&s2, cudaStreamNonBlocking);
        cudaEventCreateWithFlags(&ev_fork, cudaEventDisableTiming);
        cudaEventCreateWithFlags(&ev_join, cudaEventDisableTiming);
    }

    dim3 ge4((E + 1023) / 1024, 2);
    dim3 gs((n + 1023) / 1024, 2);
    dim3 g3((n + 255) / 256, 2);
    dim3 gg((n + 63) / 64, 2);
    dim3 gw((n * 32 + 255) / 256, 2);

    // CSR build head
    hist_kernel<<<ge4, 256>>>(ei, fei, E, n);      // rank claim
    scan1_kernel<<<gs, 1024>>>(n);                 // deg scan + dinv (warp-shuffle)

    // fork: gemm1 (needs only dinv) overlaps scan3 + claim
    cudaEventRecord(ev_fork, 0);
    cudaStreamWaitEvent(s2, ev_fork, 0);
    gemm64_kernel<<<gg, 256, 0, s2>>>(x, fx, 0, W1, n, 0);
    cudaEventRecord(ev_join, s2);

    scan3_kernel<<<g3, 256>>>(n, E);               // rowptr + deg reset
    claim_kernel<<<ge4, 256>>>(ei, fei, E, n);     // atomic-free CSR scatter

    cudaStreamWaitEvent(0, ev_join, 0);
    agg_kernel<<<gw, 256>>>(b1, n, nullptr, nullptr, nullptr, nullptr, nullptr, nullptr, nullptr);

    // layer 2 (+ fused heads)
    gemm64_kernel<<<gg, 256>>>(nullptr, nullptr, 1, W2, n, 1);
    agg_kernel<<<gw, 256>>>(b2, n, Wy, by, Wp, bp, Wb, bb, out);
}

// round 17
// speedup vs baseline: 1.6492x; 1.2161x over previous
#include <cuda_runtime.h>
#include <cuda_fp16.h>
#include <cstdint>

#define N_CAP 100000
#define E_CAP 1600000

// ---------------- scratch (__device__ globals, zero-initialized) ----------------
__device__ float  g_dinv[2][N_CAP];
__device__ int    g_deg[2][N_CAP];        // zero at entry; scan3 re-zeroes
__device__ int    g_incl[2][N_CAP];
__device__ int    g_rowptr[2][N_CAP + 1];
__device__ int    g_bsum[2][128];
__device__ int    g_rank[2][E_CAP];       // per-edge rank within its dst row
__device__ int    g_esrc[2][E_CAP];       // dst-sorted src ids
__device__ __half g_A[2][(size_t)N_CAP * 64];   // h' = dinv * (X @ W1), fp16 (layer 1)
__device__ float  g_B[2][(size_t)N_CAP * 64];   // Z1 (fp32)
__device__ float4 g_T[2][N_CAP];          // per-node head scalars t (layer 2)
__device__ float4 g_hc;                   // head constants (b2.Wy+by, b2.Wp+bp, b2.Wb+bb)

static __device__ __forceinline__ int clampi(int v, int lo, int hi) {
    return v < lo ? lo : (v > hi ? hi : v);
}

// ---------------- hist: per-edge rank claim (4 edges/thread, atomic MLP) ---------

__global__ void hist_kernel(const int* __restrict__ e0, const int* __restrict__ e1,
                            int E, int n) {
    int g = blockIdx.y;
    const int* dst = (g == 0 ? e0 : e1) + E;
    int base_e = blockIdx.x * 1024 + threadIdx.x;
#pragma unroll
    for (int k = 0; k < 4; k++) {
        int e = base_e + k * 256;
        if (e < E) {
            int d = clampi(dst[e], 0, n - 1);
            g_rank[g][e] = atomicAdd(&g_deg[g][d], 1);
        }
    }
}

// ---------------- scan1: per-1024-chunk inclusive scan + dinv (warp-shuffle) -----

__global__ void scan1_kernel(int n) {
    __shared__ int warp_sums[32];
    int g = blockIdx.y;
    int i = blockIdx.x * 1024 + threadIdx.x;
    int lane = threadIdx.x & 31;
    int wid  = threadIdx.x >> 5;
    int v = (i < n) ? g_deg[g][i] : 0;
    if (i < n) g_dinv[g][i] = rsqrtf((float)v + 1.0f);  // self-loop

    int s = v;
#pragma unroll
    for (int o = 1; o < 32; o <<= 1) {
        int t = __shfl_up_sync(0xFFFFFFFFu, s, o);
        if (lane >= o) s += t;
    }
    if (lane == 31) warp_sums[wid] = s;
    __syncthreads();
    if (wid == 0) {
        int ws = warp_sums[lane];
#pragma unroll
        for (int o = 1; o < 32; o <<= 1) {
            int t = __shfl_up_sync(0xFFFFFFFFu, ws, o);
            if (lane >= o) ws += t;
        }
        warp_sums[lane] = ws;
    }
    __syncthreads();
    if (wid > 0) s += warp_sums[wid - 1];

    if (i < n) g_incl[g][i] = s;
    if (threadIdx.x == 1023) g_bsum[g][blockIdx.x] = s;
}

// ---------------- scan3: rowptr finalize + deg reset ----------------

__global__ void scan3_kernel(int n, int E) {
    __shared__ int sh_off;
    int g = blockIdx.y;
    int t = threadIdx.x;
    int chunk = (blockIdx.x * 256) >> 10;
    if (t < 32) {
        int s = 0;
        for (int k = t; k < chunk; k += 32) s += g_bsum[g][k];
#pragma unroll
        for (int o = 16; o; o >>= 1) s += __shfl_down_sync(0xFFFFFFFFu, s, o);
        if (t == 0) sh_off = s;
    }
    __syncthreads();
    int off = sh_off;
    int i = blockIdx.x * 256 + t;
    if (i < n) {
        g_rowptr[g][i] = g_incl[g][i] - g_deg[g][i] + off;  // exclusive
        g_deg[g][i] = 0;                                     // reset invariant
    }
    if (i == 0) g_rowptr[g][n] = E;
}

// ---------------- claim: atomic-free CSR scatter (4 edges/thread MLP) ------------

__global__ void claim_kernel(const int* __restrict__ e0, const int* __restrict__ e1,
                             int E, int n) {
    int g = blockIdx.y;
    const int* base = (g == 0 ? e0 : e1);
    int base_e = blockIdx.x * 1024 + threadIdx.x;
#pragma unroll
    for (int k = 0; k < 4; k++) {
        int e = base_e + k * 256;
        if (e < E) {
            int s = clampi(base[e], 0, n - 1);
            int d = clampi(base[E + e], 0, n - 1);
            int pos = g_rowptr[g][d] + g_rank[g][e];
            g_esrc[g][pos] = s;
        }
    }
}

// ---------------- GEMM 1: h' = dinv * (X @ W1), fp16 out ----------------

__global__ void gemm1_kernel(const float* __restrict__ X0, const float* __restrict__ X1,
                             const float* __restrict__ W, int n) {
    __shared__ float Ws[64][64];
    __shared__ float Xs[64][65];
    int g = blockIdx.y;
    const float* X = (g == 0 ? X0 : X1);
    __half* Y = g_A[g];
    int tid = threadIdx.x;
    for (int i = tid; i < 64 * 16; i += 256)
        ((float4*)Ws)[i] = ((const float4*)W)[i];
    int row0 = blockIdx.x * 64;
    for (int i = tid; i < 64 * 16; i += 256) {
        int r = i >> 4, c = (i & 15) * 4;
        float4 v = make_float4(0.f, 0.f, 0.f, 0.f);
        if (row0 + r < n) v = *(const float4*)&X[(size_t)(row0 + r) * 64 + c];
        Xs[r][c] = v.x; Xs[r][c + 1] = v.y; Xs[r][c + 2] = v.z; Xs[r][c + 3] = v.w;
    }
    __syncthreads();
    int tr = (tid >> 4) * 4;
    int tc = tid & 15;
    float acc[4][4] = {};
#pragma unroll
    for (int k = 0; k < 64; k++) {
        float4 w4 = ((const float4*)&Ws[k][0])[tc];
        float x0 = Xs[tr + 0][k], x1 = Xs[tr + 1][k];
        float x2 = Xs[tr + 2][k], x3 = Xs[tr + 3][k];
        acc[0][0] += x0 * w4.x; acc[0][1] += x0 * w4.y; acc[0][2] += x0 * w4.z; acc[0][3] += x0 * w4.w;
        acc[1][0] += x1 * w4.x; acc[1][1] += x1 * w4.y; acc[1][2] += x1 * w4.z; acc[1][3] += x1 * w4.w;
        acc[2][0] += x2 * w4.x; acc[2][1] += x2 * w4.y; acc[2][2] += x2 * w4.z; acc[2][3] += x2 * w4.w;
        acc[3][0] += x3 * w4.x; acc[3][1] += x3 * w4.y; acc[3][2] += x3 * w4.z; acc[3][3] += x3 * w4.w;
    }
#pragma unroll
    for (int i = 0; i < 4; i++) {
        int r = row0 + tr + i;
        if (r < n) {
            float dv = g_dinv[g][r];
            __half2 p0 = __floats2half2_rn(acc[i][0] * dv, acc[i][1] * dv);
            __half2 p1 = __floats2half2_rn(acc[i][2] * dv, acc[i][3] * dv);
            uint2 u = make_uint2(*(unsigned*)&p0, *(unsigned*)&p1);
            *(uint2*)&Y[(size_t)r * 64 + tc * 4] = u;
        }
    }
}

// ---------------- GEMM 2: t = dinv * ((relu(Z1) @ W2) . Wheads), fp32 ------------
// Per-row head scalars computed in-epilogue via width-16 shfl reduction.
// No fp16 rounding in layer 2. Also computes head constants (block 0, g==0).

__global__ void gemm2_kernel(const float* __restrict__ W,
                             const float* __restrict__ b2,
                             const float* __restrict__ Wy, const float* __restrict__ by,
                             const float* __restrict__ Wp, const float* __restrict__ bp,
                             const float* __restrict__ Wb, const float* __restrict__ bb,
                             int n) {
    __shared__ float Ws[64][64];
    __shared__ float Xs[64][65];
    int g = blockIdx.y;
    int tid = threadIdx.x;

    // head constants: c = b2 . Whead + bias (once, by g0 block0 warp0)
    if (g == 0 && blockIdx.x == 0 && tid < 32) {
        int l = tid;
        float sy = b2[l] * Wy[l] + b2[l + 32] * Wy[l + 32];
        float sp = b2[l] * Wp[l] + b2[l + 32] * Wp[l + 32];
        float sb = b2[l] * Wb[l] + b2[l + 32] * Wb[l + 32];
#pragma unroll
        for (int o = 16; o; o >>= 1) {
            sy += __shfl_down_sync(0xFFFFFFFFu, sy, o);
            sp += __shfl_down_sync(0xFFFFFFFFu, sp, o);
            sb += __shfl_down_sync(0xFFFFFFFFu, sb, o);
        }
        if (l == 0) g_hc = make_float4(sy + by[0], sp + bp[0], sb + bb[0], 0.f);
    }

    const float* X = g_B[g];
    for (int i = tid; i < 64 * 16; i += 256)
        ((float4*)Ws)[i] = ((const float4*)W)[i];
    int row0 = blockIdx.x * 64;
    for (int i = tid; i < 64 * 16; i += 256) {
        int r = i >> 4, c = (i & 15) * 4;
        float4 v = make_float4(0.f, 0.f, 0.f, 0.f);
        if (row0 + r < n) v = *(const float4*)&X[(size_t)(row0 + r) * 64 + c];
        v.x = fmaxf(v.x, 0.f); v.y = fmaxf(v.y, 0.f);
        v.z = fmaxf(v.z, 0.f); v.w = fmaxf(v.w, 0.f);
        Xs[r][c] = v.x; Xs[r][c + 1] = v.y; Xs[r][c + 2] = v.z; Xs[r][c + 3] = v.w;
    }
    __syncthreads();
    int tr = (tid >> 4) * 4;
    int tc = tid & 15;
    float acc[4][4] = {};
#pragma unroll
    for (int k = 0; k < 64; k++) {
        float4 w4 = ((const float4*)&Ws[k][0])[tc];
        float x0 = Xs[tr + 0][k], x1 = Xs[tr + 1][k];
        float x2 = Xs[tr + 2][k], x3 = Xs[tr + 3][k];
        acc[0][0] += x0 * w4.x; acc[0][1] += x0 * w4.y; acc[0][2] += x0 * w4.z; acc[0][3] += x0 * w4.w;
        acc[1][0] += x1 * w4.x; acc[1][1] += x1 * w4.y; acc[1][2] += x1 * w4.z; acc[1][3] += x1 * w4.w;
        acc[2][0] += x2 * w4.x; acc[2][1] += x2 * w4.y; acc[2][2] += x2 * w4.z; acc[2][3] += x2 * w4.w;
        acc[3][0] += x3 * w4.x; acc[3][1] += x3 * w4.y; acc[3][2] += x3 * w4.z; acc[3][3] += x3 * w4.w;
    }

    // epilogue: per-row head dots, reduced over the 16-lane row segment
    float4 wp4 = *(const float4*)&Wp[tc * 4];
    float4 wy4, wb4;
    if (g == 0) {
        wy4 = *(const float4*)&Wy[tc * 4];
        wb4 = *(const float4*)&Wb[tc * 4];
    }
#pragma unroll
    for (int i = 0; i < 4; i++) {
        float pp = acc[i][0] * wp4.x + acc[i][1] * wp4.y + acc[i][2] * wp4.z + acc[i][3] * wp4.w;
        float py = 0.f, pb = 0.f;
        if (g == 0) {
            py = acc[i][0] * wy4.x + acc[i][1] * wy4.y + acc[i][2] * wy4.z + acc[i][3] * wy4.w;
            pb = acc[i][0] * wb4.x + acc[i][1] * wb4.y + acc[i][2] * wb4.z + acc[i][3] * wb4.w;
        }
#pragma unroll
        for (int o = 8; o; o >>= 1) {
            pp += __shfl_down_sync(0xFFFFFFFFu, pp, o, 16);
            py += __shfl_down_sync(0xFFFFFFFFu, py, o, 16);
            pb += __shfl_down_sync(0xFFFFFFFFu, pb, o, 16);
        }
        if (tc == 0) {
            int r = row0 + tr + i;
            if (r < n) {
                float dv = g_dinv[g][r];
                g_T[g][r] = (g == 0) ? make_float4(py * dv, pp * dv, pb * dv, 0.f)
                                     : make_float4(pp * dv, 0.f, 0.f, 0.f);
            }
        }
    }
}

// ---------------- agg1: Z1 = dinv[d]*(Σ h'[src] + h'[d]) + b1 (fp32 out) --------
// R9 shape (confirmed optimum): warp per node; 16/16 lane split, 2 edge rows/load.

__global__ void agg1_kernel(const float* __restrict__ b, int n) {
    int g = blockIdx.y;
    int node = (blockIdx.x * blockDim.x + threadIdx.x) >> 5;
    int lane = threadIdx.x & 31;
    if (node >= n) return;
    const uint2* __restrict__ h4 = (const uint2*)g_A[g];
    const int*   __restrict__ ep = g_esrc[g];

    int half = lane >> 4;
    int c4   = lane & 15;
    float a0 = 0.f, a1 = 0.f, a2 = 0.f, a3 = 0.f;

    int beg = g_rowptr[g][node];
    int end = g_rowptr[g][node + 1];

    for (int jj = beg; jj < end; jj += 8) {
#pragma unroll
        for (int s = 0; s < 4; s++) {
            int my = jj + s * 2 + half;
            if (my < end) {
                int src = ep[my];
                uint2 u = h4[(size_t)src * 16 + c4];
                float2 f0 = __half22float2(*(__half2*)&u.x);
                float2 f1 = __half22float2(*(__half2*)&u.y);
                a0 += f0.x; a1 += f0.y; a2 += f1.x; a3 += f1.y;
            }
        }
    }
    a0 += __shfl_xor_sync(0xFFFFFFFFu, a0, 16);
    a1 += __shfl_xor_sync(0xFFFFFFFFu, a1, 16);
    a2 += __shfl_xor_sync(0xFFFFFFFFu, a2, 16);
    a3 += __shfl_xor_sync(0xFFFFFFFFu, a3, 16);

    uint2 us = h4[(size_t)node * 16 + c4];
    float2 s0 = __half22float2(*(__half2*)&us.x);
    float2 s1 = __half22float2(*(__half2*)&us.y);
    float dd = g_dinv[g][node];
    const float4 bv = *(const float4*)&b[c4 * 4];
    if (half == 0) {
        float4 z = make_float4(fmaf(dd, a0 + s0.x, bv.x), fmaf(dd, a1 + s0.y, bv.y),
                               fmaf(dd, a2 + s1.x, bv.z), fmaf(dd, a3 + s1.y, bv.w));
        *(float4*)&g_B[g][(size_t)node * 64 + c4 * 4] = z;
    }
}

// ---------------- agg2 (scalar): out = relu(dinv[d]*(Σ t[src] + t[d]) + c) -------
// thread per node; float4 gathers from 1.6MB L2-resident table; 4-slot MLP

__global__ void aggscalar_kernel(float* __restrict__ out, int n) {
    int g = blockIdx.y;
    int node = blockIdx.x * 256 + threadIdx.x;
    if (node >= n) return;
    const float4* __restrict__ t = g_T[g];
    const int*    __restrict__ ep = g_esrc[g];
    int beg = g_rowptr[g][node];
    int end = g_rowptr[g][node + 1];

    float4 s0 = t[node];  // self term
    float sx1 = 0.f, sy1 = 0.f, sz1 = 0.f;
    float sx2 = 0.f, sy2 = 0.f, sz2 = 0.f;
    float sx3 = 0.f, sy3 = 0.f, sz3 = 0.f;
    int j = beg;
    for (; j + 4 <= end; j += 4) {
        float4 a = t[ep[j]];
        float4 b = t[ep[j + 1]];
        float4 c = t[ep[j + 2]];
        float4 d = t[ep[j + 3]];
        s0.x += a.x; s0.y += a.y; s0.z += a.z;
        sx1 += b.x; sy1 += b.y; sz1 += b.z;
        sx2 += c.x; sy2 += c.y; sz2 += c.z;
        sx3 += d.x; sy3 += d.y; sz3 += d.z;
    }
    for (; j < end; j++) {
        float4 a = t[ep[j]];
        s0.x += a.x; s0.y += a.y; s0.z += a.z;
    }
    float sx = s0.x + sx1 + sx2 + sx3;
    float dd = g_dinv[g][node];
    float4 hc = g_hc;
    if (g == 0) {
        float sy = s0.y + sy1 + sy2 + sy3;
        float sz = s0.z + sz1 + sz2 + sz3;
        out[node]                 = fmaxf(fmaf(dd, sx, hc.x), 0.f);  // yi
        out[(size_t)n + node]     = fmaxf(fmaf(dd, sy, hc.y), 0.f);  // fprob
        out[(size_t)3 * n + node] = fmaxf(fmaf(dd, sz, hc.z), 0.f);  // treat_prob
    } else {
        out[(size_t)2 * n + node] = fmaxf(fmaf(dd, sx, hc.y), 0.f);  // fprob_f
    }
}

// ---------------- launch (R13 structure: single fork for gemm1 only) -------------

extern "C" void kernel_launch(void* const* d_in, const int* in_sizes, int n_in,
                              void* d_out, int out_size) {
    const float* x   = (const float*)d_in[0];
    const int*   ei  = (const int*)d_in[1];    // int32 on the wire
    const float* fx  = (const float*)d_in[2];
    const int*   fei = (const int*)d_in[3];
    const float* W1 = (const float*)d_in[4];
    const float* b1 = (const float*)d_in[5];
    const float* W2 = (const float*)d_in[6];
    const float* b2 = (const float*)d_in[7];
    const float* Wy = (const float*)d_in[8];
    const float* by = (const float*)d_in[9];
    const float* Wp = (const float*)d_in[10];
    const float* bp = (const float*)d_in[11];
    const float* Wb = (const float*)d_in[12];
    const float* bb = (const float*)d_in[13];

    int n = in_sizes[0] / 64;
    int E = in_sizes[1] / 2;
    float* out = (float*)d_out;

    static cudaStream_t s2 = nullptr;
    static cudaEvent_t ev_fork = nullptr, ev_join = nullptr;
    if (!s2) {
        cudaStreamCreateWithFlags(&s2, cudaStreamNonBlocking);
        cudaEventCreateWithFlags(&ev_fork, cudaEventDisableTiming);
        cudaEventCreateWithFlags(&ev_join, cudaEventDisableTiming);
    }

    dim3 ge4((E + 1023) / 1024, 2);
    dim3 gs((n + 1023) / 1024, 2);
    dim3 g3((n + 255) / 256, 2);
    dim3 gg((n + 63) / 64, 2);
    dim3 gw((n * 32 + 255) / 256, 2);
    dim3 gn((n + 255) / 256, 2);

    // CSR build head
    hist_kernel<<<ge4, 256>>>(ei, fei, E, n);      // rank claim
    scan1_kernel<<<gs, 1024>>>(n);                 // deg scan + dinv

    // fork: gemm1 (needs only dinv) overlaps scan3 + claim
    cudaEventRecord(ev_fork, 0);
    cudaStreamWaitEvent(s2, ev_fork, 0);
    gemm1_kernel<<<gg, 256, 0, s2>>>(x, fx, W1, n);
    cudaEventRecord(ev_join, s2);

    scan3_kernel<<<g3, 256>>>(n, E);               // rowptr + deg reset
    claim_kernel<<<ge4, 256>>>(ei, fei, E, n);     // atomic-free CSR scatter

    cudaStreamWaitEvent(0, ev_join, 0);
    agg1_kernel<<<gw, 256>>>(b1, n);               // Z1 (fp32)

    // layer 2: per-node head scalars (fp32, no fp16), then scalar aggregation
    gemm2_kernel<<<gg, 256>>>(W2, b2, Wy, by, Wp, bp, Wb, bb, n);
    aggscalar_kernel<<<gn, 256>>>(out, n);
}